// round 16
// baseline (speedup 1.0000x reference)
#include <cuda_runtime.h>
#include <cstdint>

// Problem constants
#define B_TOT  2048
#define S_LEN  256
#define DIN    3
#define HID    128
#define D_OUT  6
#define DT_F   0.1f

// R15 base: 14 rows/CTA, 147 CTAs, 256 threads, 1 CTA/SM, two independent
// 128-thread groups (bar.sync rh+1, 128); pre-barrier x-projection;
// vectorized finish (4 consecutive neurons, LDS.128 partial reads).
// R16: PHASE STAGGER — group 1 runs a ~1600-cycle dependent-FMA delay before
// the scan, so the groups sit in the ANTI-PHASE fixed point: one group's
// finish/barrier phase executes under the other group's matvec, keeping the
// FFMA2 pipe continuously fed instead of idling in lockstep.
#define ROWS   14
#define RPG    7
#define NCTA   ((B_TOT + ROWS - 1) / ROWS)   // 147
#define NTHR   256
#define SPC    (2 * HID)                     // splat pitch: 256 floats
#define PQP    (ROWS * HID)                  // partial slice pitch

#define XSZ    (ROWS * S_LEN * DIN)          // 10752 floats
#define HSPSZ  (ROWS * SPC)                  // 3584 floats per buffer
#define PARTSZ (8 * PQP)                     // 14336 floats
#define SMEMF  (XSZ + 2 * HSPSZ + PARTSZ)    // 32256 floats = 129024 B

typedef unsigned long long u64;

// ---- packed f32x2 ops ----
__device__ __forceinline__ u64 fma2(u64 a, u64 b, u64 c) {
    u64 d;
    asm("fma.rn.f32x2 %0, %1, %2, %3;" : "=l"(d) : "l"(a), "l"(b), "l"(c));
    return d;
}
__device__ __forceinline__ u64 add2(u64 a, u64 b) {
    u64 d;
    asm("add.rn.f32x2 %0, %1, %2;" : "=l"(d) : "l"(a), "l"(b));
    return d;
}
__device__ __forceinline__ u64 pk(float lo, float hi) {
    u64 v;
    asm("mov.b64 %0, {%1, %2};" : "=l"(v) : "f"(lo), "f"(hi));
    return v;
}
__device__ __forceinline__ void upk(u64 v, float& lo, float& hi) {
    asm("mov.b64 {%0, %1}, %2;" : "=f"(lo), "=f"(hi) : "l"(v));
}

// Accurate-enough tanh: ex2.approx + fast divide; abs err ~1e-6.
__device__ __forceinline__ float fast_tanh(float x) {
    float ax = fminf(fabsf(x), 15.0f);
    float e  = __expf(2.0f * ax);
    float t  = 1.0f - __fdividef(2.0f, e + 1.0f);
    return copysignf(t, x);
}

// softplus(x) = max(x,0) + log1p(exp(-|x|))  (stable, accurate)
__device__ __forceinline__ float softplus_acc(float x) {
    return fmaxf(x, 0.0f) + log1pf(__expf(-fabsf(x)));
}

extern __shared__ float smem_dyn[];

__global__ void __launch_bounds__(NTHR, 1)
cfc_kernel(const float* __restrict__ x,        // [B, S, 3]
           const float* __restrict__ W_xh,     // [128, 3]
           const float* __restrict__ W_hh,     // [128, 128]
           const float* __restrict__ b_hh,     // [128]
           const float* __restrict__ log_tau,  // [128]
           const float* __restrict__ fc_W,     // [6, 128]
           const float* __restrict__ fc_b,     // [6]
           float* __restrict__ out)            // [B, 6]
{
    float* xsh  = smem_dyn;            // x tile
    float* hsp0 = xsh + XSZ;           // splatted h, buffer 0
    float* hsp1 = hsp0 + HSPSZ;        // splatted h, buffer 1
    float* part = hsp1 + HSPSZ;        // partials [ks][row][neuron]

    const int tid  = threadIdx.x;
    const int np   = tid & 15;            // neuron oct: n0 = 8np .. 8np+7
    const int ks   = (tid >> 4) & 7;      // K slice: cols [16ks, 16ks+16)
    const int rh   = tid >> 7;            // GROUP id (row half)
    const int n0   = 8 * np;
    const int rowb = rh * RPG;            // group's base row
    const int cb   = blockIdx.x * ROWS;   // global batch-row base

    // ---- W_hh: 4 neuron-pairs x 16 cols -> 64 u64 = 128 regs ----
    u64 W0[16], W1[16], W2[16], W3[16];
    #pragma unroll
    for (int c = 0; c < 16; c++) {
        const int col = 16 * ks + c;
        W0[c] = pk(W_hh[(n0 + 0) * HID + col], W_hh[(n0 + 1) * HID + col]);
        W1[c] = pk(W_hh[(n0 + 2) * HID + col], W_hh[(n0 + 3) * HID + col]);
        W2[c] = pk(W_hh[(n0 + 4) * HID + col], W_hh[(n0 + 5) * HID + col]);
        W3[c] = pk(W_hh[(n0 + 6) * HID + col], W_hh[(n0 + 7) * HID + col]);
    }

    // ---- finish assignment (IN-GROUP): 4 consecutive neurons, rows by warp ----
    const int gtid = tid & 127;
    const int p2   = gtid & 31;           // neuron quad base: neurons 4p2..4p2+3
    const int rsel = gtid >> 5;           // warp-in-group: rows {rsel, rsel+4}
    const int ntask = (rsel == 3) ? 1 : 2;
    float fw[12], fb4[4], fa4[4];
    #pragma unroll
    for (int i = 0; i < 4; i++) {
        const int n = 4 * p2 + i;
        fw[3 * i + 0] = W_xh[n * 3 + 0];
        fw[3 * i + 1] = W_xh[n * 3 + 1];
        fw[3 * i + 2] = W_xh[n * 3 + 2];
        fb4[i] = b_hh[n];
        fa4[i] = DT_F / (softplus_acc(log_tau[n]) + 0.001f);
    }
    float ho[2][4];                       // old h per task x 4 neurons, registers
    #pragma unroll
    for (int t = 0; t < 2; t++)
        #pragma unroll
        for (int i = 0; i < 4; i++) ho[t][i] = 0.0f;

    // ---- stage x tile (zero-pad partial last CTA); zero h buffers ----
    {
        const float* src = x + (size_t)cb * (S_LEN * DIN);
        int lim = (B_TOT - cb) * (S_LEN * DIN);
        if (lim > XSZ) lim = XSZ;
        for (int i = tid; i < XSZ; i += NTHR)
            xsh[i] = (i < lim) ? src[i] : 0.0f;
    }
    for (int i = tid; i < 2 * HSPSZ; i += NTHR) hsp0[i] = 0.0f;
    __syncthreads();

    // ---- R16: phase stagger. Group 1 burns ~1600 dependent-FMA cycles so
    // the two groups run anti-phased (finish under matvec) for the scan. ----
    if (rh == 1) {
        float v = (float)tid * 1e-30f;
        #pragma unroll 1
        for (int i = 0; i < 400; i++)
            v = fmaf(v, 0.9999999f, 1e-30f);
        if (v == 12345.678f) xsh[0] = v;   // unreachable; defeats DCE
    }

    // ================= sequential scan over S (group-independent) =================
    for (int s = 0; s < S_LEN; s++) {
        const float* hcur = (s & 1) ? hsp1 : hsp0;
        float*       hnxt = (s & 1) ? hsp0 : hsp1;

        const float* hb = hcur + rowb * SPC + 32 * ks;
        float* pb = part + ks * PQP + rowb * HID + n0;

        // ---- matvec batch A: rows 0..3 of this group ----
        {
            u64 a0[4], a1[4], a2[4], a3[4];
            #pragma unroll
            for (int r = 0; r < 4; r++) { a0[r] = 0; a1[r] = 0; a2[r] = 0; a3[r] = 0; }
            #pragma unroll
            for (int c2 = 0; c2 < 8; c2++) {
                #pragma unroll
                for (int r = 0; r < 4; r++) {
                    ulonglong2 hv = *reinterpret_cast<const ulonglong2*>(hb + r * SPC + c2 * 4);
                    a0[r] = fma2(W0[2 * c2],     hv.x, a0[r]);
                    a1[r] = fma2(W1[2 * c2],     hv.x, a1[r]);
                    a2[r] = fma2(W2[2 * c2],     hv.x, a2[r]);
                    a3[r] = fma2(W3[2 * c2],     hv.x, a3[r]);
                    a0[r] = fma2(W0[2 * c2 + 1], hv.y, a0[r]);
                    a1[r] = fma2(W1[2 * c2 + 1], hv.y, a1[r]);
                    a2[r] = fma2(W2[2 * c2 + 1], hv.y, a2[r]);
                    a3[r] = fma2(W3[2 * c2 + 1], hv.y, a3[r]);
                }
            }
            #pragma unroll
            for (int r = 0; r < 4; r++) {
                ulonglong2 v1; v1.x = a0[r]; v1.y = a1[r];
                ulonglong2 v2; v2.x = a2[r]; v2.y = a3[r];
                *reinterpret_cast<ulonglong2*>(pb + r * HID)     = v1;
                *reinterpret_cast<ulonglong2*>(pb + r * HID + 4) = v2;
            }
        }
        // ---- matvec batch B: rows 4..6 of this group ----
        {
            u64 a0[3], a1[3], a2[3], a3[3];
            #pragma unroll
            for (int r = 0; r < 3; r++) { a0[r] = 0; a1[r] = 0; a2[r] = 0; a3[r] = 0; }
            #pragma unroll
            for (int c2 = 0; c2 < 8; c2++) {
                #pragma unroll
                for (int r = 0; r < 3; r++) {
                    ulonglong2 hv = *reinterpret_cast<const ulonglong2*>(hb + (4 + r) * SPC + c2 * 4);
                    a0[r] = fma2(W0[2 * c2],     hv.x, a0[r]);
                    a1[r] = fma2(W1[2 * c2],     hv.x, a1[r]);
                    a2[r] = fma2(W2[2 * c2],     hv.x, a2[r]);
                    a3[r] = fma2(W3[2 * c2],     hv.x, a3[r]);
                    a0[r] = fma2(W0[2 * c2 + 1], hv.y, a0[r]);
                    a1[r] = fma2(W1[2 * c2 + 1], hv.y, a1[r]);
                    a2[r] = fma2(W2[2 * c2 + 1], hv.y, a2[r]);
                    a3[r] = fma2(W3[2 * c2 + 1], hv.y, a3[r]);
                }
            }
            #pragma unroll
            for (int r = 0; r < 3; r++) {
                ulonglong2 v1; v1.x = a0[r]; v1.y = a1[r];
                ulonglong2 v2; v2.x = a2[r]; v2.y = a3[r];
                *reinterpret_cast<ulonglong2*>(pb + (4 + r) * HID)     = v1;
                *reinterpret_cast<ulonglong2*>(pb + (4 + r) * HID + 4) = v2;
            }
        }

        // ---- pre-barrier: x-projection for this thread's finish tasks ----
        float zx[2][4];
        #pragma unroll
        for (int t = 0; t < 2; t++) {
            if (t >= ntask) break;
            const int row = rowb + rsel + 4 * t;
            const float* xr = xsh + row * (S_LEN * DIN) + s * 3;
            float x0 = xr[0], x1 = xr[1], x2 = xr[2];
            #pragma unroll
            for (int i = 0; i < 4; i++)
                zx[t][i] = fmaf(fw[3 * i], x0,
                           fmaf(fw[3 * i + 1], x1,
                           fmaf(fw[3 * i + 2], x2, fb4[i])));
        }

        // group-scoped barrier: partials of THIS group's rows ready
        asm volatile("bar.sync %0, 128;" :: "r"(rh + 1) : "memory");

        // ---- finish: ntask rows, 4 consecutive neurons, LDS.128 reads ----
        #pragma unroll
        for (int t = 0; t < 2; t++) {
            if (t >= ntask) break;
            const int row = rowb + rsel + 4 * t;
            const float* pr = part + row * HID + 4 * p2;
            ulonglong2 acc = *reinterpret_cast<const ulonglong2*>(pr);
            #pragma unroll
            for (int q = 1; q < 8; q++) {
                ulonglong2 v = *reinterpret_cast<const ulonglong2*>(pr + q * PQP);
                acc.x = add2(acc.x, v.x);
                acc.y = add2(acc.y, v.y);
            }
            float z[4];
            upk(acc.x, z[0], z[1]);
            upk(acc.y, z[2], z[3]);
            u64 sp[4];
            #pragma unroll
            for (int i = 0; i < 4; i++) {
                float f = fast_tanh(z[i] + zx[t][i]);
                ho[t][i] = fmaf(fa4[i], f - ho[t][i], ho[t][i]);
                sp[i] = pk(ho[t][i], ho[t][i]);
            }
            float* hd = hnxt + row * SPC + 8 * p2;
            ulonglong2 o;
            o.x = sp[0]; o.y = sp[1];
            *reinterpret_cast<ulonglong2*>(hd)     = o;
            o.x = sp[2]; o.y = sp[3];
            *reinterpret_cast<ulonglong2*>(hd + 4) = o;
        }
        // group-scoped barrier: this group's h(s+1) rows complete
        asm volatile("bar.sync %0, 128;" :: "r"(rh + 1) : "memory");
    }

    __syncthreads();   // join groups before the head

    // ================= output head: softplus(h_T @ fc_W^T + fc_b) =================
    const float* hf = hsp0;   // S_LEN even -> final state in buffer 0 (splatted)
    if (tid < ROWS * D_OUT) {
        const int rr = tid / D_OUT;
        const int o  = tid % D_OUT;
        const int grow = cb + rr;
        if (grow < B_TOT) {
            float z = fc_b[o];
            const float* wrow = fc_W + o * HID;
            const float* hrow = hf + rr * SPC;
            #pragma unroll
            for (int j = 0; j < HID; j++)
                z = fmaf(wrow[j], hrow[2 * j], z);
            out[grow * D_OUT + o] = softplus_acc(z);
        }
    }
}

extern "C" void kernel_launch(void* const* d_in, const int* in_sizes, int n_in,
                              void* d_out, int out_size) {
    const float* x       = (const float*)d_in[0];
    const float* W_xh    = (const float*)d_in[1];
    const float* W_hh    = (const float*)d_in[2];
    const float* b_hh    = (const float*)d_in[3];
    const float* log_tau = (const float*)d_in[4];
    const float* fc_W    = (const float*)d_in[5];
    const float* fc_b    = (const float*)d_in[6];
    float* out = (float*)d_out;

    const size_t shmem = (size_t)SMEMF * sizeof(float);  // 129024 B
    cudaFuncSetAttribute(cfc_kernel, cudaFuncAttributeMaxDynamicSharedMemorySize, (int)shmem);

    cfc_kernel<<<NCTA, NTHR, shmem>>>(x, W_xh, W_hh, b_hh, log_tau, fc_W, fc_b, out);
}

// round 17
// speedup vs baseline: 1.7428x; 1.7428x over previous
#include <cuda_runtime.h>
#include <cstdint>

// Problem constants
#define B_TOT  2048
#define S_LEN  256
#define DIN    3
#define HID    128
#define D_OUT  6
#define DT_F   0.1f

// R15 base (best, 485.5us): 14 rows/CTA, 147 CTAs, 256 threads, 1 CTA/SM,
// two 128-thread groups in natural lockstep (mutual latency hiding),
// pre-barrier x-projection, vectorized finish.
// R17: partial buffer split by QUAD PARITY. v1 (quad 2np) -> plo, v2 (quad
// 2np+1) -> phi, each at 16B lane stride -> partial STS is conflict-free
// (4 wavefronts per STS.128 instead of 8). phi offset +64B mod 128B so the
// finish's alternating plo/phi reads still cover all 32 banks.
#define ROWS   14
#define RPG    7
#define NCTA   ((B_TOT + ROWS - 1) / ROWS)   // 147
#define NTHR   256
#define SPC    (2 * HID)                     // splat pitch: 256 floats
#define PQ2    (ROWS * 64)                   // 896 floats per slice per parity

#define XSZ    (ROWS * S_LEN * DIN)          // 10752 floats
#define HSPSZ  (ROWS * SPC)                  // 3584 floats per buffer
#define PARTSZ (16 * PQ2 + 16)               // plo[8] + 64B gap + phi[8] = 14352
#define SMEMF  (XSZ + 2 * HSPSZ + PARTSZ)    // 32272 floats = 129088 B

typedef unsigned long long u64;

// ---- packed f32x2 ops ----
__device__ __forceinline__ u64 fma2(u64 a, u64 b, u64 c) {
    u64 d;
    asm("fma.rn.f32x2 %0, %1, %2, %3;" : "=l"(d) : "l"(a), "l"(b), "l"(c));
    return d;
}
__device__ __forceinline__ u64 add2(u64 a, u64 b) {
    u64 d;
    asm("add.rn.f32x2 %0, %1, %2;" : "=l"(d) : "l"(a), "l"(b));
    return d;
}
__device__ __forceinline__ u64 pk(float lo, float hi) {
    u64 v;
    asm("mov.b64 %0, {%1, %2};" : "=l"(v) : "f"(lo), "f"(hi));
    return v;
}
__device__ __forceinline__ void upk(u64 v, float& lo, float& hi) {
    asm("mov.b64 {%0, %1}, %2;" : "=f"(lo), "=f"(hi) : "l"(v));
}

// Accurate-enough tanh: ex2.approx + fast divide; abs err ~1e-6.
__device__ __forceinline__ float fast_tanh(float x) {
    float ax = fminf(fabsf(x), 15.0f);
    float e  = __expf(2.0f * ax);
    float t  = 1.0f - __fdividef(2.0f, e + 1.0f);
    return copysignf(t, x);
}

// softplus(x) = max(x,0) + log1p(exp(-|x|))  (stable, accurate)
__device__ __forceinline__ float softplus_acc(float x) {
    return fmaxf(x, 0.0f) + log1pf(__expf(-fabsf(x)));
}

extern __shared__ float smem_dyn[];

__global__ void __launch_bounds__(NTHR, 1)
cfc_kernel(const float* __restrict__ x,        // [B, S, 3]
           const float* __restrict__ W_xh,     // [128, 3]
           const float* __restrict__ W_hh,     // [128, 128]
           const float* __restrict__ b_hh,     // [128]
           const float* __restrict__ log_tau,  // [128]
           const float* __restrict__ fc_W,     // [6, 128]
           const float* __restrict__ fc_b,     // [6]
           float* __restrict__ out)            // [B, 6]
{
    float* xsh  = smem_dyn;            // x tile
    float* hsp0 = xsh + XSZ;           // splatted h, buffer 0
    float* hsp1 = hsp0 + HSPSZ;        // splatted h, buffer 1
    float* plo  = hsp1 + HSPSZ;        // partials, even quads: [ks][row][np]
    float* phi  = plo + 8 * PQ2 + 16;  // partials, odd quads (+64B bank shift)

    const int tid  = threadIdx.x;
    const int np   = tid & 15;            // neuron oct: n0 = 8np .. 8np+7
    const int ks   = (tid >> 4) & 7;      // K slice: cols [16ks, 16ks+16)
    const int rh   = tid >> 7;            // GROUP id (row half)
    const int n0   = 8 * np;
    const int rowb = rh * RPG;            // group's base row
    const int cb   = blockIdx.x * ROWS;   // global batch-row base

    // ---- W_hh: 4 neuron-pairs x 16 cols -> 64 u64 = 128 regs ----
    u64 W0[16], W1[16], W2[16], W3[16];
    #pragma unroll
    for (int c = 0; c < 16; c++) {
        const int col = 16 * ks + c;
        W0[c] = pk(W_hh[(n0 + 0) * HID + col], W_hh[(n0 + 1) * HID + col]);
        W1[c] = pk(W_hh[(n0 + 2) * HID + col], W_hh[(n0 + 3) * HID + col]);
        W2[c] = pk(W_hh[(n0 + 4) * HID + col], W_hh[(n0 + 5) * HID + col]);
        W3[c] = pk(W_hh[(n0 + 6) * HID + col], W_hh[(n0 + 7) * HID + col]);
    }

    // ---- finish assignment (IN-GROUP): 4 consecutive neurons, rows by warp ----
    const int gtid = tid & 127;
    const int p2   = gtid & 31;           // neuron quad: neurons 4p2..4p2+3
    const int rsel = gtid >> 5;           // warp-in-group: rows {rsel, rsel+4}
    const int ntask = (rsel == 3) ? 1 : 2;
    float fw[12], fb4[4], fa4[4];
    #pragma unroll
    for (int i = 0; i < 4; i++) {
        const int n = 4 * p2 + i;
        fw[3 * i + 0] = W_xh[n * 3 + 0];
        fw[3 * i + 1] = W_xh[n * 3 + 1];
        fw[3 * i + 2] = W_xh[n * 3 + 2];
        fb4[i] = b_hh[n];
        fa4[i] = DT_F / (softplus_acc(log_tau[n]) + 0.001f);
    }
    float ho[2][4];                       // old h per task x 4 neurons, registers
    #pragma unroll
    for (int t = 0; t < 2; t++)
        #pragma unroll
        for (int i = 0; i < 4; i++) ho[t][i] = 0.0f;
    // finish read base: quad parity selects buffer, slot = p2>>1 (16B stride)
    const float* fpbase = ((p2 & 1) ? phi : plo) + 4 * (p2 >> 1);

    // ---- stage x tile (zero-pad partial last CTA); zero h buffers ----
    {
        const float* src = x + (size_t)cb * (S_LEN * DIN);
        int lim = (B_TOT - cb) * (S_LEN * DIN);
        if (lim > XSZ) lim = XSZ;
        for (int i = tid; i < XSZ; i += NTHR)
            xsh[i] = (i < lim) ? src[i] : 0.0f;
    }
    for (int i = tid; i < 2 * HSPSZ; i += NTHR) hsp0[i] = 0.0f;
    __syncthreads();

    // ================= sequential scan over S (group-independent) =================
    for (int s = 0; s < S_LEN; s++) {
        const float* hcur = (s & 1) ? hsp1 : hsp0;
        float*       hnxt = (s & 1) ? hsp0 : hsp1;

        const float* hb = hcur + rowb * SPC + 32 * ks;
        float* plo_b = plo + ks * PQ2 + rowb * 64 + 4 * np;
        float* phi_b = phi + ks * PQ2 + rowb * 64 + 4 * np;

        // ---- matvec batch A: rows 0..3 of this group ----
        {
            u64 a0[4], a1[4], a2[4], a3[4];
            #pragma unroll
            for (int r = 0; r < 4; r++) { a0[r] = 0; a1[r] = 0; a2[r] = 0; a3[r] = 0; }
            #pragma unroll
            for (int c2 = 0; c2 < 8; c2++) {
                #pragma unroll
                for (int r = 0; r < 4; r++) {
                    ulonglong2 hv = *reinterpret_cast<const ulonglong2*>(hb + r * SPC + c2 * 4);
                    a0[r] = fma2(W0[2 * c2],     hv.x, a0[r]);
                    a1[r] = fma2(W1[2 * c2],     hv.x, a1[r]);
                    a2[r] = fma2(W2[2 * c2],     hv.x, a2[r]);
                    a3[r] = fma2(W3[2 * c2],     hv.x, a3[r]);
                    a0[r] = fma2(W0[2 * c2 + 1], hv.y, a0[r]);
                    a1[r] = fma2(W1[2 * c2 + 1], hv.y, a1[r]);
                    a2[r] = fma2(W2[2 * c2 + 1], hv.y, a2[r]);
                    a3[r] = fma2(W3[2 * c2 + 1], hv.y, a3[r]);
                }
            }
            #pragma unroll
            for (int r = 0; r < 4; r++) {
                ulonglong2 v1; v1.x = a0[r]; v1.y = a1[r];   // quad 2np
                ulonglong2 v2; v2.x = a2[r]; v2.y = a3[r];   // quad 2np+1
                *reinterpret_cast<ulonglong2*>(plo_b + r * 64) = v1;
                *reinterpret_cast<ulonglong2*>(phi_b + r * 64) = v2;
            }
        }
        // ---- matvec batch B: rows 4..6 of this group ----
        {
            u64 a0[3], a1[3], a2[3], a3[3];
            #pragma unroll
            for (int r = 0; r < 3; r++) { a0[r] = 0; a1[r] = 0; a2[r] = 0; a3[r] = 0; }
            #pragma unroll
            for (int c2 = 0; c2 < 8; c2++) {
                #pragma unroll
                for (int r = 0; r < 3; r++) {
                    ulonglong2 hv = *reinterpret_cast<const ulonglong2*>(hb + (4 + r) * SPC + c2 * 4);
                    a0[r] = fma2(W0[2 * c2],     hv.x, a0[r]);
                    a1[r] = fma2(W1[2 * c2],     hv.x, a1[r]);
                    a2[r] = fma2(W2[2 * c2],     hv.x, a2[r]);
                    a3[r] = fma2(W3[2 * c2],     hv.x, a3[r]);
                    a0[r] = fma2(W0[2 * c2 + 1], hv.y, a0[r]);
                    a1[r] = fma2(W1[2 * c2 + 1], hv.y, a1[r]);
                    a2[r] = fma2(W2[2 * c2 + 1], hv.y, a2[r]);
                    a3[r] = fma2(W3[2 * c2 + 1], hv.y, a3[r]);
                }
            }
            #pragma unroll
            for (int r = 0; r < 3; r++) {
                ulonglong2 v1; v1.x = a0[r]; v1.y = a1[r];
                ulonglong2 v2; v2.x = a2[r]; v2.y = a3[r];
                *reinterpret_cast<ulonglong2*>(plo_b + (4 + r) * 64) = v1;
                *reinterpret_cast<ulonglong2*>(phi_b + (4 + r) * 64) = v2;
            }
        }

        // ---- pre-barrier: x-projection for this thread's finish tasks ----
        float zx[2][4];
        #pragma unroll
        for (int t = 0; t < 2; t++) {
            if (t >= ntask) break;
            const int row = rowb + rsel + 4 * t;
            const float* xr = xsh + row * (S_LEN * DIN) + s * 3;
            float x0 = xr[0], x1 = xr[1], x2 = xr[2];
            #pragma unroll
            for (int i = 0; i < 4; i++)
                zx[t][i] = fmaf(fw[3 * i], x0,
                           fmaf(fw[3 * i + 1], x1,
                           fmaf(fw[3 * i + 2], x2, fb4[i])));
        }

        // group-scoped barrier: partials of THIS group's rows ready
        asm volatile("bar.sync %0, 128;" :: "r"(rh + 1) : "memory");

        // ---- finish: ntask rows, 4 consecutive neurons, LDS.128 reads ----
        #pragma unroll
        for (int t = 0; t < 2; t++) {
            if (t >= ntask) break;
            const int row = rowb + rsel + 4 * t;
            const float* pr = fpbase + row * 64;
            ulonglong2 acc = *reinterpret_cast<const ulonglong2*>(pr);
            #pragma unroll
            for (int q = 1; q < 8; q++) {
                ulonglong2 v = *reinterpret_cast<const ulonglong2*>(pr + q * PQ2);
                acc.x = add2(acc.x, v.x);
                acc.y = add2(acc.y, v.y);
            }
            float z[4];
            upk(acc.x, z[0], z[1]);
            upk(acc.y, z[2], z[3]);
            u64 sp[4];
            #pragma unroll
            for (int i = 0; i < 4; i++) {
                float f = fast_tanh(z[i] + zx[t][i]);
                ho[t][i] = fmaf(fa4[i], f - ho[t][i], ho[t][i]);
                sp[i] = pk(ho[t][i], ho[t][i]);
            }
            float* hd = hnxt + row * SPC + 8 * p2;
            ulonglong2 o;
            o.x = sp[0]; o.y = sp[1];
            *reinterpret_cast<ulonglong2*>(hd)     = o;
            o.x = sp[2]; o.y = sp[3];
            *reinterpret_cast<ulonglong2*>(hd + 4) = o;
        }
        // group-scoped barrier: this group's h(s+1) rows complete
        asm volatile("bar.sync %0, 128;" :: "r"(rh + 1) : "memory");
    }

    __syncthreads();   // join groups before the head

    // ================= output head: softplus(h_T @ fc_W^T + fc_b) =================
    const float* hf = hsp0;   // S_LEN even -> final state in buffer 0 (splatted)
    if (tid < ROWS * D_OUT) {
        const int rr = tid / D_OUT;
        const int o  = tid % D_OUT;
        const int grow = cb + rr;
        if (grow < B_TOT) {
            float z = fc_b[o];
            const float* wrow = fc_W + o * HID;
            const float* hrow = hf + rr * SPC;
            #pragma unroll
            for (int j = 0; j < HID; j++)
                z = fmaf(wrow[j], hrow[2 * j], z);
            out[grow * D_OUT + o] = softplus_acc(z);
        }
    }
}

extern "C" void kernel_launch(void* const* d_in, const int* in_sizes, int n_in,
                              void* d_out, int out_size) {
    const float* x       = (const float*)d_in[0];
    const float* W_xh    = (const float*)d_in[1];
    const float* W_hh    = (const float*)d_in[2];
    const float* b_hh    = (const float*)d_in[3];
    const float* log_tau = (const float*)d_in[4];
    const float* fc_W    = (const float*)d_in[5];
    const float* fc_b    = (const float*)d_in[6];
    float* out = (float*)d_out;

    const size_t shmem = (size_t)SMEMF * sizeof(float);  // 129088 B
    cudaFuncSetAttribute(cfc_kernel, cudaFuncAttributeMaxDynamicSharedMemorySize, (int)shmem);

    cfc_kernel<<<NCTA, NTHR, shmem>>>(x, W_xh, W_hh, b_hh, log_tau, fc_W, fc_b, out);
}